// round 3
// baseline (speedup 1.0000x reference)
#include <cuda_runtime.h>
#include <cuda_fp16.h>
#include <cstdint>

#define T_DIM 4096
#define H_DIM 2048
#define I_DIM 8192
#define GU_DIM (2 * I_DIM)   // 16384

// ---------------- device scratch (allocation-free rule: __device__ globals) ----
__device__ __half g_xh[(size_t)T_DIM * H_DIM];            // 16 MB
__device__ __half g_guwh[(size_t)GU_DIM * H_DIM];         // 64 MB
__device__ __half g_dwh[(size_t)H_DIM * I_DIM];           // 32 MB
__device__ __half g_guh[(size_t)T_DIM * GU_DIM];          // 128 MB (gate|up result)
__device__ __half g_interh[(size_t)T_DIM * I_DIM];        // 64 MB

// ---------------- helpers ----------------
__device__ __forceinline__ uint32_t smem_to_u32(const void* smem_ptr) {
    uint32_t addr;
    asm("{ .reg .u64 tmp; cvta.to.shared.u64 tmp, %1; cvt.u32.u64 %0, tmp; }"
        : "=r"(addr) : "l"(smem_ptr));
    return addr;
}

#define CP_ASYNC16(dst_u32, src_ptr) \
    asm volatile("cp.async.cg.shared.global [%0], [%1], 16;" \
        :: "r"(dst_u32), "l"(src_ptr) : "memory")
#define CP_ASYNC_COMMIT() asm volatile("cp.async.commit_group;" ::: "memory")
#define CP_ASYNC_WAIT_2() asm volatile("cp.async.wait_group 2;" ::: "memory")

__device__ __forceinline__ void ldmatrix_x4(uint32_t& r0, uint32_t& r1,
                                            uint32_t& r2, uint32_t& r3,
                                            uint32_t addr) {
    asm volatile("ldmatrix.sync.aligned.m8n8.x4.shared.b16 {%0,%1,%2,%3}, [%4];"
                 : "=r"(r0), "=r"(r1), "=r"(r2), "=r"(r3) : "r"(addr));
}

__device__ __forceinline__ void mma_16816(float* d, const uint32_t* a,
                                          const uint32_t* b) {
    asm volatile(
        "mma.sync.aligned.m16n8k16.row.col.f32.f16.f16.f32 "
        "{%0,%1,%2,%3}, {%4,%5,%6,%7}, {%8,%9}, {%0,%1,%2,%3};"
        : "+f"(d[0]), "+f"(d[1]), "+f"(d[2]), "+f"(d[3])
        : "r"(a[0]), "r"(a[1]), "r"(a[2]), "r"(a[3]), "r"(b[0]), "r"(b[1]));
}

// ---------------- LUT-SiLU (faithful to the 2049-entry linear interp LUT) ----
__device__ __forceinline__ float lut_silu_f(float g) {
    float t = (g + 8.0f) * 128.0f;
    t = fminf(fmaxf(t, 0.0f), 2048.0f);
    float i0 = floorf(t);
    float frac = t - i0;
    float x0 = -8.0f + i0 * 0.0078125f;
    float x1 = (i0 >= 2048.0f) ? 8.0f : (x0 + 0.0078125f);
    float l0 = x0 / (1.0f + __expf(-x0));
    float l1 = x1 / (1.0f + __expf(-x1));
    return l0 + (l1 - l0) * frac;
}

// ---------------- fp32 -> fp16 conversion ----------------
__global__ void cvt_f32_f16_kernel(const float* __restrict__ src,
                                   __half* __restrict__ dst, int n4) {
    int i = blockIdx.x * blockDim.x + threadIdx.x;
    if (i < n4) {
        float4 v = reinterpret_cast<const float4*>(src)[i];
        __half2* d2 = reinterpret_cast<__half2*>(dst) + 2 * (size_t)i;
        d2[0] = __floats2half2_rn(v.x, v.y);
        d2[1] = __floats2half2_rn(v.z, v.w);
    }
}

// ---------------- fused silu(gate)*up elementwise ----------------
__global__ void silu_mul_kernel(const __half* __restrict__ gu,
                                __half* __restrict__ inter) {
    int idx = blockIdx.x * blockDim.x + threadIdx.x;       // over T*I/8
    int t = idx / (I_DIM / 8);
    int j = (idx % (I_DIM / 8)) * 8;
    const uint4 g4 = *reinterpret_cast<const uint4*>(gu + (size_t)t * GU_DIM + j);
    const uint4 u4 = *reinterpret_cast<const uint4*>(gu + (size_t)t * GU_DIM + I_DIM + j);
    const __half2* gh = reinterpret_cast<const __half2*>(&g4);
    const __half2* uh = reinterpret_cast<const __half2*>(&u4);
    uint4 o4;
    __half2* oh = reinterpret_cast<__half2*>(&o4);
#pragma unroll
    for (int p = 0; p < 4; p++) {
        float2 gf = __half22float2(gh[p]);
        float2 uf = __half22float2(uh[p]);
        oh[p] = __floats2half2_rn(lut_silu_f(gf.x) * uf.x,
                                  lut_silu_f(gf.y) * uf.y);
    }
    *reinterpret_cast<uint4*>(inter + (size_t)t * I_DIM + j) = o4;
}

// ---------------- 128x128x32 HMMA GEMM, 4-stage cp.async pipeline ----------
// C[M,N] = A[M,K] * B[N,K]^T, all half, fp32 accumulate.
// MODE 0: out half, scale per col (gate_up). MODE 1: out float (d_out).
// 256 threads = 8 warps in 4(M) x 2(N); warp tile 32x64.
// SMEM swizzle: 64B rows, 16B chunk index ^= (row>>1)&3  -> conflict-free
// for both cp.async stores and ldmatrix loads (verified by phase analysis).
template <int MODE, int KT, int LDC>
__global__ void __launch_bounds__(256, 2)
gemm_hmma_kernel(const __half* __restrict__ A,
                 const __half* __restrict__ B,
                 const float* __restrict__ scales,
                 void* __restrict__ outp) {
    extern __shared__ char smem[];
    const uint32_t smem_base = smem_to_u32(smem);
    constexpr uint32_t STAGE = 16384;   // A 8KB + B 8KB
    constexpr int NC = KT / 32;         // K chunks of 32 halves

    const int tid = threadIdx.x;
    const int wid = tid >> 5;
    const int lane = tid & 31;
    const int warp_m = wid & 3;         // 0..3 -> m offset *32
    const int warp_n = wid >> 2;        // 0..1 -> n offset *64
    const int m0 = blockIdx.y * 128;
    const int n0 = blockIdx.x * 128;

    const __half* Ag = A + (size_t)m0 * KT;
    const __half* Bg = B + (size_t)n0 * KT;

    // ---- cp.async store addresses (per thread: row tid/4 and tid/4+64) ----
    const int st_row = tid >> 2;
    const int st_chunk = tid & 3;
    const uint32_t st_off =
        (uint32_t)st_row * 64u +
        (uint32_t)((st_chunk ^ ((st_row >> 1) & 3)) * 16);
    // +64 rows: (row>>1) changes by 32 -> xor unchanged; offset += 64*64
    const size_t g_off0 = (size_t)st_row * KT + st_chunk * 8;
    const size_t g_off1 = (size_t)(st_row + 64) * KT + st_chunk * 8;

    auto load_stage = [&](int chunk) {
        const uint32_t sb = smem_base + (uint32_t)(chunk & 3) * STAGE;
        const int k0 = chunk * 32;
        CP_ASYNC16(sb + st_off,           Ag + g_off0 + k0);
        CP_ASYNC16(sb + st_off + 4096u,   Ag + g_off1 + k0);
        CP_ASYNC16(sb + 8192u + st_off,         Bg + g_off0 + k0);
        CP_ASYNC16(sb + 8192u + st_off + 4096u, Bg + g_off1 + k0);
        CP_ASYNC_COMMIT();
    };

    // ---- ldmatrix lane address components ----
    // A (x4, matrices: (m0,k0),(m8,k0),(m0,k8),(m8,k8))
    const int a_rowb = warp_m * 32 + ((lane >> 3) & 1) * 8 + (lane & 7);
    const int a_koff = (lane >> 4) & 1;
    const int a_xor = (((((lane >> 3) & 1) * 8) + (lane & 7)) >> 1) & 3;
    // B (x4 per n-pair p: (n2p,k0),(n2p,k8),(n2p+1,k0),(n2p+1,k8))
    const int b_rowb = warp_n * 64 + ((lane >> 4) & 1) * 8 + (lane & 7);
    const int b_koff = (lane >> 3) & 1;
    const int b_xor = (((((lane >> 4) & 1) * 8) + (lane & 7)) >> 1) & 3;

    float acc[2][8][4];
#pragma unroll
    for (int mi = 0; mi < 2; mi++)
#pragma unroll
        for (int ni = 0; ni < 8; ni++)
#pragma unroll
            for (int e = 0; e < 4; e++) acc[mi][ni][e] = 0.0f;

    // prologue: fill 3 stages
    load_stage(0);
    load_stage(1);
    load_stage(2);

#pragma unroll 1
    for (int k = 0; k < NC; ++k) {
        CP_ASYNC_WAIT_2();
        __syncthreads();
        const uint32_t sb = smem_base + (uint32_t)(k & 3) * STAGE;

#pragma unroll
        for (int ks = 0; ks < 2; ks++) {
            uint32_t a[2][4];
#pragma unroll
            for (int mi = 0; mi < 2; mi++) {
                uint32_t addr = sb + (uint32_t)((a_rowb + mi * 16) * 64) +
                                (uint32_t)(((ks * 2 + a_koff) ^ a_xor) * 16);
                ldmatrix_x4(a[mi][0], a[mi][1], a[mi][2], a[mi][3], addr);
            }
            uint32_t b[8][2];
#pragma unroll
            for (int p = 0; p < 4; p++) {
                uint32_t addr = sb + 8192u +
                                (uint32_t)((b_rowb + p * 16) * 64) +
                                (uint32_t)(((ks * 2 + b_koff) ^ b_xor) * 16);
                uint32_t r0, r1, r2, r3;
                ldmatrix_x4(r0, r1, r2, r3, addr);
                b[2 * p][0] = r0; b[2 * p][1] = r1;
                b[2 * p + 1][0] = r2; b[2 * p + 1][1] = r3;
            }
#pragma unroll
            for (int mi = 0; mi < 2; mi++)
#pragma unroll
                for (int ni = 0; ni < 8; ni++)
                    mma_16816(acc[mi][ni], a[mi], b[ni]);
        }

        if (k + 3 < NC) load_stage(k + 3);
        else CP_ASYNC_COMMIT();   // keep group accounting aligned
    }

    // ---- epilogue ----
    const int gr = lane >> 2;
    const int gc = (lane & 3) * 2;
#pragma unroll
    for (int mi = 0; mi < 2; mi++) {
#pragma unroll
        for (int ni = 0; ni < 8; ni++) {
            const int row = m0 + warp_m * 32 + mi * 16 + gr;
            const int col = n0 + warp_n * 64 + ni * 8 + gc;
            const float s0 = __ldg(&scales[col]);
            const float s1 = __ldg(&scales[col + 1]);
            if (MODE == 0) {
                __half* out = reinterpret_cast<__half*>(outp);
                *reinterpret_cast<__half2*>(&out[(size_t)row * LDC + col]) =
                    __floats2half2_rn(acc[mi][ni][0] * s0, acc[mi][ni][1] * s1);
                *reinterpret_cast<__half2*>(&out[(size_t)(row + 8) * LDC + col]) =
                    __floats2half2_rn(acc[mi][ni][2] * s0, acc[mi][ni][3] * s1);
            } else {
                float* out = reinterpret_cast<float*>(outp);
                *reinterpret_cast<float2*>(&out[(size_t)row * LDC + col]) =
                    make_float2(acc[mi][ni][0] * s0, acc[mi][ni][1] * s1);
                *reinterpret_cast<float2*>(&out[(size_t)(row + 8) * LDC + col]) =
                    make_float2(acc[mi][ni][2] * s0, acc[mi][ni][3] * s1);
            }
        }
    }
}

// ---------------- launch ----------------
extern "C" void kernel_launch(void* const* d_in, const int* in_sizes, int n_in,
                              void* d_out, int out_size) {
    const float* x   = (const float*)d_in[0];
    const float* guw = (const float*)d_in[1];
    const float* gus = (const float*)d_in[2];
    const float* dw  = (const float*)d_in[3];
    const float* ds  = (const float*)d_in[4];

    __half *xh, *guwh, *dwh, *guh, *interh;
    cudaGetSymbolAddress((void**)&xh, g_xh);
    cudaGetSymbolAddress((void**)&guwh, g_guwh);
    cudaGetSymbolAddress((void**)&dwh, g_dwh);
    cudaGetSymbolAddress((void**)&guh, g_guh);
    cudaGetSymbolAddress((void**)&interh, g_interh);

    // fp32 -> fp16 prep (weights are int-valued: exact in fp16)
    {
        int n4 = T_DIM * H_DIM / 4;
        cvt_f32_f16_kernel<<<(n4 + 255) / 256, 256>>>(x, xh, n4);
    }
    {
        int n4 = GU_DIM * H_DIM / 4;
        cvt_f32_f16_kernel<<<(n4 + 255) / 256, 256>>>(guw, guwh, n4);
    }
    {
        int n4 = H_DIM * I_DIM / 4;
        cvt_f32_f16_kernel<<<(n4 + 255) / 256, 256>>>(dw, dwh, n4);
    }

    const int SMEM_BYTES = 4 * 16384;   // 64 KB
    cudaFuncSetAttribute(gemm_hmma_kernel<0, H_DIM, GU_DIM>,
                         cudaFuncAttributeMaxDynamicSharedMemorySize, SMEM_BYTES);
    cudaFuncSetAttribute(gemm_hmma_kernel<1, I_DIM, H_DIM>,
                         cudaFuncAttributeMaxDynamicSharedMemorySize, SMEM_BYTES);

    // GEMM1: gu = x @ gate_up_w^T * scale   (4096 x 16384, K=2048)
    {
        dim3 grid(GU_DIM / 128, T_DIM / 128);
        gemm_hmma_kernel<0, H_DIM, GU_DIM><<<grid, 256, SMEM_BYTES>>>(
            xh, guwh, gus, guh);
    }
    // inter = lut_silu(gate) * up
    {
        int n = T_DIM * I_DIM / 8;
        silu_mul_kernel<<<n / 256, 256>>>(guh, interh);
    }
    // GEMM2: out = inter @ down_w^T * scale (4096 x 2048, K=8192)
    {
        dim3 grid(H_DIM / 128, T_DIM / 128);
        gemm_hmma_kernel<1, I_DIM, H_DIM><<<grid, 256, SMEM_BYTES>>>(
            interh, dwh, ds, d_out);
    }
    (void)in_sizes; (void)n_in; (void)out_size;
}